// round 8
// baseline (speedup 1.0000x reference)
#include <cuda_runtime.h>
#include <cuda_fp16.h>
#include <cstdint>
#include <cstddef>

#define B_   128
#define S_   1024
#define IN_  256
#define H_   1024
#define G4_  4096
#define OUT_ 256
#define NC_  128     // CTAs (1/SM)
#define NSTG 8       // A pipeline stages (16KB each)
#define CHB  16384   // chunk: 128 rows x 64 cols fp16, SW128 image
#define NKC  20      // chunks per step: 4 x + 16 h

// ---------------- device globals -------------------------------------------
// g_x: [t][kc(4)][16KB swizzled]   g_h: [buf][kc(16)][16KB swizzled]
__device__ __align__(1024) char g_x [(size_t)S_*4*CHB];
__device__ __align__(1024) char g_h [2][16*CHB];
__device__ __align__(16)  __half g_WxT[(size_t)G4_*IN_];   // [n][k]
__device__ __align__(16)  __half g_WhT[(size_t)G4_*H_];    // [n][k]
__device__ unsigned g_cntA[16];     // per-chunk arrival counters (monotonic)

__device__ __host__ __forceinline__ int swz(int o){ return o ^ ((o >> 3) & 0x70); }

// ---------------- helpers ---------------------------------------------------
__device__ __forceinline__ void cp16(void* smem, const void* gmem){
    unsigned s = (unsigned)__cvta_generic_to_shared(smem);
    asm volatile("cp.async.cg.shared.global [%0], [%1], 16;\n" :: "r"(s), "l"(gmem));
}
__device__ __forceinline__ void cp_commit(){ asm volatile("cp.async.commit_group;\n"); }
template<int N> __device__ __forceinline__ void cp_wait(){ asm volatile("cp.async.wait_group %0;\n" :: "n"(N)); }

__device__ __forceinline__ void mbar_init(uint32_t mbar, uint32_t cnt){
    asm volatile("mbarrier.init.shared.b64 [%0], %1;\n" :: "r"(mbar), "r"(cnt) : "memory");
}
__device__ __forceinline__ void mbar_expect_tx(uint32_t mbar, uint32_t tx){
    asm volatile("mbarrier.arrive.expect_tx.shared.b64 _, [%0], %1;\n" :: "r"(mbar), "r"(tx) : "memory");
}
__device__ __forceinline__ void mbar_arrive(uint32_t mbar){
    asm volatile("mbarrier.arrive.shared.b64 _, [%0];\n" :: "r"(mbar) : "memory");
}
__device__ __forceinline__ void bulk_g2s(uint32_t sdst, const void* gsrc, uint32_t bytes, uint32_t mbar){
    asm volatile("cp.async.bulk.shared::cluster.global.mbarrier::complete_tx::bytes [%0], [%1], %2, [%3];\n"
                 :: "r"(sdst), "l"(gsrc), "r"(bytes), "r"(mbar) : "memory");
}
__device__ __forceinline__ void mbar_wait(uint32_t mbar, uint32_t parity){
    asm volatile(
        "{\n\t.reg .pred P1;\n\t"
        "LAB_W_%=:\n\t"
        "mbarrier.try_wait.parity.acquire.cta.shared::cta.b64 P1, [%0], %1;\n\t"
        "@P1 bra LAB_D_%=;\n\t"
        "bra LAB_W_%=;\n\t"
        "LAB_D_%=:\n\t}"
        :: "r"(mbar), "r"(parity) : "memory");
}
__device__ __forceinline__ void mma16816(float* c, uint32_t a0, uint32_t a1, uint32_t a2, uint32_t a3,
                                         uint32_t b0, uint32_t b1){
    asm volatile(
        "mma.sync.aligned.m16n8k16.row.col.f32.f16.f16.f32 "
        "{%0,%1,%2,%3}, {%4,%5,%6,%7}, {%8,%9}, {%0,%1,%2,%3};\n"
        : "+f"(c[0]), "+f"(c[1]), "+f"(c[2]), "+f"(c[3])
        : "r"(a0), "r"(a1), "r"(a2), "r"(a3), "r"(b0), "r"(b1));
}
__device__ __forceinline__ float sigm_(float x){ return 1.f / (1.f + __expf(-x)); }
__device__ __forceinline__ float tanh_(float x){ return 2.f / (1.f + __expf(-2.f*x)) - 1.f; }

// ---------------- phase 0: converts ----------------------------------------
__global__ void conv_x_kernel(const float* __restrict__ x){
    size_t n = (size_t)B_*S_*IN_;
    for (size_t i = (size_t)blockIdx.x*blockDim.x + threadIdx.x; i < n; i += (size_t)gridDim.x*blockDim.x){
        int k  = (int)(i % IN_);
        size_t bs = i / IN_;
        int s  = (int)(bs % S_);
        int b  = (int)(bs / S_);
        char* chunk = g_x + ((size_t)s*4 + (k >> 6))*CHB;
        int o = b*128 + (k & 63)*2;
        *(__half*)(chunk + swz(o)) = __float2half(x[i]);
    }
}
__global__ void conv_w_kernel(const float* __restrict__ Wx, const float* __restrict__ Wh){
    size_t n1 = (size_t)G4_*IN_, n2 = (size_t)G4_*H_;
    for (size_t i = (size_t)blockIdx.x*blockDim.x + threadIdx.x; i < n1 + n2; i += (size_t)gridDim.x*blockDim.x){
        if (i < n1){
            int n = (int)(i / IN_), k = (int)(i % IN_);
            g_WxT[i] = __float2half(Wx[(size_t)k*G4_ + n]);
        } else {
            size_t j = i - n1;
            int n = (int)(j / H_), k = (int)(j % H_);
            g_WhT[j] = __float2half(Wh[(size_t)k*G4_ + n]);
        }
    }
}
__global__ void zero_h_kernel(){
    size_t n = sizeof(g_h)/4;
    unsigned* p = (unsigned*)g_h;
    for (size_t i = (size_t)blockIdx.x*blockDim.x + threadIdx.x; i < n; i += (size_t)gridDim.x*blockDim.x)
        p[i] = 0u;
    if (blockIdx.x == 0 && threadIdx.x < 16) g_cntA[threadIdx.x] = 0u;
}

// ---------------- recurrence: 4 compute warps + 1 producer warp ------------
// Chunk-granular cross-CTA dependency: h-chunk c of step t+1 is ready when the
// 8 CTAs of group c (bid>>3 == c) arrive at g_cntA[c] (count reaches (t+1)*8).
// The producer gates each h-chunk TMA on its own counter only -> the global
// barrier dissolves into the pipeline. Chunks consumed in rotated order.
constexpr int LDW_ = H_  + 8;
constexpr int LDX_ = IN_ + 8;
constexpr int A_OFF  = 0;
constexpr int WH_OFF = NSTG*CHB;                 // 131072
constexpr int WX_OFF = WH_OFF + 32*LDW_*2;       // 197120
constexpr int MB_OFF = WX_OFF + 32*LDX_*2;       // 214016
constexpr int SMEM_REC = MB_OFF + 2*NSTG*8 + 32;

__global__ __launch_bounds__(160,1) void lstm_rec_kernel(const float* __restrict__ bias){
    extern __shared__ __align__(16) char sh[];
    int tid = threadIdx.x, lane = tid & 31, w = tid >> 5;
    int gid = lane >> 2, ctid = lane & 3;
    int j0 = blockIdx.x * 8;
    int cbase = ((blockIdx.x >> 3) + 1) & 15;    // rotated h-chunk start

    uint32_t a_smem  = (uint32_t)__cvta_generic_to_shared(sh + A_OFF);
    uint32_t mb_full = (uint32_t)__cvta_generic_to_shared(sh + MB_OFF);       // +8*i
    uint32_t mb_emp  = mb_full + NSTG*8;                                      // +8*i
    __half* Whs = (__half*)(sh + WH_OFF);
    __half* Wxs = (__half*)(sh + WX_OFF);

    if (tid == 0){
        for (int i = 0; i < NSTG; i++){ mbar_init(mb_full + i*8, 1); mbar_init(mb_emp + i*8, 4); }
        asm volatile("fence.proxy.async.shared::cta;\n" ::: "memory");
    }
    // weight slices (padded, conflict-free B LDS)
    for (int idx = tid; idx < 32*128; idx += 160){
        int r = idx >> 7, seg = idx & 127;
        cp16(&Whs[r*LDW_ + seg*8], g_WhT + ((size_t)((r>>3)*H_ + j0 + (r&7)))*H_ + seg*8);
    }
    for (int idx = tid; idx < 32*32; idx += 160){
        int r = idx >> 5, seg = idx & 31;
        cp16(&Wxs[r*LDX_ + seg*8], g_WxT + ((size_t)((r>>3)*H_ + j0 + (r&7)))*IN_ + seg*8);
    }
    cp_commit(); cp_wait<0>();
    __syncthreads();   // the ONLY full-block sync

    if (w == 4){
        // ----------------- producer warp (lane 0 only) -----------------
        if (lane == 0){
            int pst = 0, pwrap = 0;
            for (int t = 0; t < S_; t++){
                for (int kc = 0; kc < NKC; kc++){
                    const char* src;
                    if (kc < 4){
                        src = g_x + ((size_t)t*4 + kc)*CHB;
                    } else {
                        int c = (cbase + kc - 4) & 15;
                        if (t > 0){
                            unsigned v, tgtv = (unsigned)t * 8u;
                            do { asm volatile("ld.acquire.gpu.global.u32 %0, [%1];\n" : "=r"(v) : "l"(&g_cntA[c]) : "memory"); }
                            while (v < tgtv);
                        }
                        src = g_h[t & 1] + c*CHB;
                    }
                    if (pwrap > 0) mbar_wait(mb_emp + pst*8, (unsigned)((pwrap - 1) & 1));
                    mbar_expect_tx(mb_full + pst*8, CHB);
                    bulk_g2s(a_smem + pst*CHB, src, CHB, mb_full + pst*8);
                    if (++pst == NSTG){ pst = 0; pwrap++; }
                }
            }
        }
        return;
    }

    // ----------------- compute warps (w = 0..3, 32 batch rows each) --------
    float2 bf = *(const float2*)&bias[0*H_ + j0 + ctid*2];
    float2 bi = *(const float2*)&bias[1*H_ + j0 + ctid*2];
    float2 bg = *(const float2*)&bias[2*H_ + j0 + ctid*2];
    float2 bo = *(const float2*)&bias[3*H_ + j0 + ctid*2];

    float cst[8];                       // [mt*4 + rh*2 + ji]
    #pragma unroll
    for (int i = 0; i < 8; i++) cst[i] = 0.f;

    int cstg = 0, cwrap = 0;
    int mrow = w * 32;

    for (int t = 0; t < S_; t++){
        float acc[2][4][4];
        #pragma unroll
        for (int mt = 0; mt < 2; mt++)
            #pragma unroll
            for (int nt = 0; nt < 4; nt++){ acc[mt][nt][0]=0; acc[mt][nt][1]=0; acc[mt][nt][2]=0; acc[mt][nt][3]=0; }

        for (int kc = 0; kc < NKC; kc++){
            mbar_wait(mb_full + cstg*8, (unsigned)(cwrap & 1));
            const char* A = sh + A_OFF + cstg*CHB;
            const __half* Bb;
            int ldb, kbase;
            if (kc < 4){ Bb = Wxs; ldb = LDX_; kbase = kc*64; }
            else       { Bb = Whs; ldb = LDW_; kbase = (((cbase + kc - 4) & 15))*64; }
            #pragma unroll
            for (int kk = 0; kk < 64; kk += 16){
                uint32_t b0[4], b1[4];
                #pragma unroll
                for (int nt = 0; nt < 4; nt++){
                    const __half* wr = Bb + (nt*8 + gid)*ldb + kbase + kk + ctid*2;
                    b0[nt] = *(const uint32_t*)wr;
                    b1[nt] = *(const uint32_t*)(wr + 8);
                }
                #pragma unroll
                for (int mt = 0; mt < 2; mt++){
                    int r = mrow + mt*16 + gid;
                    int cb = (kk + ctid*2)*2;
                    uint32_t a0 = *(const uint32_t*)(A + swz( r     *128 + cb     ));
                    uint32_t a1 = *(const uint32_t*)(A + swz((r + 8)*128 + cb     ));
                    uint32_t a2 = *(const uint32_t*)(A + swz( r     *128 + cb + 16));
                    uint32_t a3 = *(const uint32_t*)(A + swz((r + 8)*128 + cb + 16));
                    #pragma unroll
                    for (int nt = 0; nt < 4; nt++)
                        mma16816(acc[mt][nt], a0, a1, a2, a3, b0[nt], b1[nt]);
                }
            }
            if (lane == 0) mbar_arrive(mb_emp + cstg*8);
            if (++cstg == NSTG){ cstg = 0; cwrap++; }
        }

        // epilogue: + bias -> activations -> c,h update (register-local)
        char* hdst = g_h[(t + 1) & 1] + (j0 >> 6)*CHB;
        #pragma unroll
        for (int mt = 0; mt < 2; mt++){
            #pragma unroll
            for (int rh = 0; rh < 2; rh++){
                int m = mrow + mt*16 + gid + rh*8;
                __half2 hv;
                #pragma unroll
                for (int ji = 0; ji < 2; ji++){
                    int c = rh*2 + ji, s = mt*4 + rh*2 + ji;
                    float fg = sigm_(acc[mt][0][c] + (ji ? bf.y : bf.x));
                    float ig = sigm_(acc[mt][1][c] + (ji ? bi.y : bi.x));
                    float gg = tanh_(acc[mt][2][c] + (ji ? bg.y : bg.x));
                    float og = sigm_(acc[mt][3][c] + (ji ? bo.y : bo.x));
                    float cn = fg*cst[s] + ig*gg;
                    cst[s] = cn;
                    float hn = og * tanh_(cn);
                    if (ji == 0) hv.x = __float2half(hn); else hv.y = __float2half(hn);
                }
                *(uint32_t*)(hdst + swz(m*128 + (j0 & 63)*2 + ctid*4)) = *(uint32_t*)&hv;
            }
        }

        asm volatile("bar.sync 1, 128;\n" ::: "memory");   // compute warps only
        if (tid == 0){
            __threadfence();
            asm volatile("red.release.gpu.global.add.u32 [%0], %1;\n"
                         :: "l"(&g_cntA[blockIdx.x >> 3]), "r"(1u) : "memory");
        }
    }
}

// ---------------- final FC: out = h_T @ Wfc + bfc (fp32) -------------------
__global__ __launch_bounds__(256) void fc_kernel(const float* __restrict__ Wfc,
                                                 const float* __restrict__ bfc,
                                                 float* __restrict__ out){
    __shared__ float hsm[H_];
    int b = blockIdx.x, o = threadIdx.x;
    for (int k = o; k < H_; k += 256){
        const char* chunk = g_h[0] + (k >> 6)*CHB;   // S even -> final h in buf 0
        hsm[k] = __half2float(*(const __half*)(chunk + swz(b*128 + (k & 63)*2)));
    }
    __syncthreads();
    float s = bfc[o];
    #pragma unroll 8
    for (int k = 0; k < H_; k++) s = fmaf(hsm[k], Wfc[(size_t)k*OUT_ + o], s);
    out[(size_t)b*OUT_ + o] = s;
}

// ---------------- entry -----------------------------------------------------
extern "C" void kernel_launch(void* const* d_in, const int* in_sizes, int n_in,
                              void* d_out, int out_size){
    (void)in_sizes; (void)n_in; (void)out_size;
    const float* x   = (const float*)d_in[0];
    const float* Wx  = (const float*)d_in[1];
    const float* Wh  = (const float*)d_in[2];
    const float* b   = (const float*)d_in[3];
    const float* Wfc = (const float*)d_in[4];
    const float* bfc = (const float*)d_in[5];
    float* out = (float*)d_out;

    cudaFuncSetAttribute(lstm_rec_kernel, cudaFuncAttributeMaxDynamicSharedMemorySize, SMEM_REC);

    conv_x_kernel<<<2048, 256>>>(x);
    conv_w_kernel<<<1024, 256>>>(Wx, Wh);
    zero_h_kernel<<<256, 256>>>();
    lstm_rec_kernel<<<NC_, 160, SMEM_REC>>>(b);
    fc_kernel<<<B_, 256>>>(Wfc, bfc, out);
}

// round 9
// speedup vs baseline: 1.0893x; 1.0893x over previous
#include <cuda_runtime.h>
#include <cuda_fp16.h>
#include <cstdint>
#include <cstddef>

#define B_   128
#define S_   1024
#define IN_  256
#define H_   1024
#define G4_  4096
#define OUT_ 256
#define NC_  128     // CTAs (1/SM): (bh 2) x (jgrp 64)
#define GRP_ 64      // CTAs per batch-half group
#define NSTG 7       // A pipeline stages (8KB each)
#define CHB  8192    // chunk: 64 rows x 64 cols fp16, SW128 image
#define NKC  20      // chunks per step: 4 x + 16 h

// ---------------- device globals -------------------------------------------
// g_x: [t][bh][kc(4)][8KB swizzled]   g_h: [buf][bh][kc(16)][8KB swizzled]
__device__ __align__(1024) char g_x [(size_t)S_*2*4*CHB];   // 64 MB
__device__ __align__(1024) char g_h [2][2][16*CHB];          // 512 KB
__device__ __align__(16)  __half g_WxT[(size_t)G4_*IN_];     // [n][k]
__device__ __align__(16)  __half g_WhT[(size_t)G4_*H_];      // [n][k]
__device__ unsigned g_cnt[2];       // per-group arrival counters (monotonic)

__device__ __host__ __forceinline__ int swz(int o){ return o ^ ((o >> 3) & 0x70); }

// ---------------- helpers ---------------------------------------------------
__device__ __forceinline__ void cp16(void* smem, const void* gmem){
    unsigned s = (unsigned)__cvta_generic_to_shared(smem);
    asm volatile("cp.async.cg.shared.global [%0], [%1], 16;\n" :: "r"(s), "l"(gmem));
}
__device__ __forceinline__ void cp_commit(){ asm volatile("cp.async.commit_group;\n"); }
template<int N> __device__ __forceinline__ void cp_wait(){ asm volatile("cp.async.wait_group %0;\n" :: "n"(N)); }

__device__ __forceinline__ void mbar_init(uint32_t mbar, uint32_t cnt){
    asm volatile("mbarrier.init.shared.b64 [%0], %1;\n" :: "r"(mbar), "r"(cnt) : "memory");
}
__device__ __forceinline__ void mbar_expect_tx(uint32_t mbar, uint32_t tx){
    asm volatile("mbarrier.arrive.expect_tx.shared.b64 _, [%0], %1;\n" :: "r"(mbar), "r"(tx) : "memory");
}
__device__ __forceinline__ void mbar_arrive(uint32_t mbar){
    asm volatile("mbarrier.arrive.shared.b64 _, [%0];\n" :: "r"(mbar) : "memory");
}
__device__ __forceinline__ void bulk_g2s(uint32_t sdst, const void* gsrc, uint32_t bytes, uint32_t mbar){
    asm volatile("cp.async.bulk.shared::cluster.global.mbarrier::complete_tx::bytes [%0], [%1], %2, [%3];\n"
                 :: "r"(sdst), "l"(gsrc), "r"(bytes), "r"(mbar) : "memory");
}
__device__ __forceinline__ void mbar_wait(uint32_t mbar, uint32_t parity){
    asm volatile(
        "{\n\t.reg .pred P1;\n\t"
        "LAB_W_%=:\n\t"
        "mbarrier.try_wait.parity.acquire.cta.shared::cta.b64 P1, [%0], %1;\n\t"
        "@P1 bra LAB_D_%=;\n\t"
        "bra LAB_W_%=;\n\t"
        "LAB_D_%=:\n\t}"
        :: "r"(mbar), "r"(parity) : "memory");
}
__device__ __forceinline__ void mma16816(float* c, uint32_t a0, uint32_t a1, uint32_t a2, uint32_t a3,
                                         uint32_t b0, uint32_t b1){
    asm volatile(
        "mma.sync.aligned.m16n8k16.row.col.f32.f16.f16.f32 "
        "{%0,%1,%2,%3}, {%4,%5,%6,%7}, {%8,%9}, {%0,%1,%2,%3};\n"
        : "+f"(c[0]), "+f"(c[1]), "+f"(c[2]), "+f"(c[3])
        : "r"(a0), "r"(a1), "r"(a2), "r"(a3), "r"(b0), "r"(b1));
}
__device__ __forceinline__ float sigm_(float x){ return 1.f / (1.f + __expf(-x)); }
__device__ __forceinline__ float tanh_(float x){ return 2.f / (1.f + __expf(-2.f*x)) - 1.f; }

// ---------------- phase 0: converts ----------------------------------------
__global__ void conv_x_kernel(const float* __restrict__ x){
    size_t n = (size_t)B_*S_*IN_;
    for (size_t i = (size_t)blockIdx.x*blockDim.x + threadIdx.x; i < n; i += (size_t)gridDim.x*blockDim.x){
        int k  = (int)(i % IN_);
        size_t bs = i / IN_;
        int s  = (int)(bs % S_);
        int b  = (int)(bs / S_);
        int bh = b >> 6, row = b & 63;
        char* chunk = g_x + (((size_t)s*2 + bh)*4 + (k >> 6))*CHB;
        *(__half*)(chunk + swz(row*128 + (k & 63)*2)) = __float2half(x[i]);
    }
}
__global__ void conv_w_kernel(const float* __restrict__ Wx, const float* __restrict__ Wh){
    size_t n1 = (size_t)G4_*IN_, n2 = (size_t)G4_*H_;
    for (size_t i = (size_t)blockIdx.x*blockDim.x + threadIdx.x; i < n1 + n2; i += (size_t)gridDim.x*blockDim.x){
        if (i < n1){
            int n = (int)(i / IN_), k = (int)(i % IN_);
            g_WxT[i] = __float2half(Wx[(size_t)k*G4_ + n]);
        } else {
            size_t j = i - n1;
            int n = (int)(j / H_), k = (int)(j % H_);
            g_WhT[j] = __float2half(Wh[(size_t)k*G4_ + n]);
        }
    }
}
__global__ void zero_h_kernel(){
    size_t n = sizeof(g_h)/4;
    unsigned* p = (unsigned*)g_h;
    for (size_t i = (size_t)blockIdx.x*blockDim.x + threadIdx.x; i < n; i += (size_t)gridDim.x*blockDim.x)
        p[i] = 0u;
    if (blockIdx.x == 0 && threadIdx.x < 2) g_cnt[threadIdx.x] = 0u;
}

// ---------------- recurrence ------------------------------------------------
// CTA (bh, jgrp): batch rows [bh*64, bh*64+64), hidden units [jgrp*16, +16)
// = 64 gate cols ordered col = hid_local*4 + gate (f,i,g,o interleaved).
// 8 compute warps, warp tile 32(M) x 16(N): wm = w>>2, wn = w&3.
// Producer warp (w=8) streams 20 x 8KB bulk chunks/step through 7-stage ring.
// Per-group (64 CTA) barrier: red.add counter, producer polls before h-chunks.
constexpr int A_OFF  = 0;
constexpr int WH_OFF = NSTG*CHB;                 // 57344
constexpr int WX_OFF = WH_OFF + 16*CHB;          // 188416
constexpr int ST_OFF = WX_OFF + 4*CHB;           // 221184 (2KB staging)
constexpr int MB_OFF = ST_OFF + 2048;            // 223232
constexpr int SMEM_REC = MB_OFF + 2*NSTG*8 + 16; // 223360

__global__ __launch_bounds__(288,1) void lstm_rec_kernel(const float* __restrict__ bias){
    extern __shared__ __align__(16) char sh[];
    int tid = threadIdx.x, lane = tid & 31, w = tid >> 5;
    int gid = lane >> 2, ctid = lane & 3;
    int bh = blockIdx.x & 1, jgrp = blockIdx.x >> 1;
    int j0 = jgrp * 16;

    uint32_t a_smem  = (uint32_t)__cvta_generic_to_shared(sh + A_OFF);
    uint32_t mb_full = (uint32_t)__cvta_generic_to_shared(sh + MB_OFF);   // +8*i
    uint32_t mb_emp  = mb_full + NSTG*8;                                  // +8*i
    char* Whs = sh + WH_OFF;
    char* Wxs = sh + WX_OFF;
    char* stg = sh + ST_OFF;

    if (tid == 0){
        for (int i = 0; i < NSTG; i++){ mbar_init(mb_full + i*8, 1); mbar_init(mb_emp + i*8, 8); }
        asm volatile("fence.proxy.async.shared::cta;\n" ::: "memory");
    }
    // weight slices into swizzled chunk format (row n = hid*4+gate, 64 rows)
    for (int idx = tid; idx < 64*128; idx += 288){
        int n = idx >> 7, u = idx & 127;
        int hid = n >> 2, g = n & 3, k = u*8;
        cp16(Whs + (k >> 6)*CHB + swz(n*128 + (k & 63)*2),
             g_WhT + ((size_t)(g*H_ + j0 + hid))*H_ + k);
    }
    for (int idx = tid; idx < 64*32; idx += 288){
        int n = idx >> 5, u = idx & 31;
        int hid = n >> 2, g = n & 3, k = u*8;
        cp16(Wxs + (k >> 6)*CHB + swz(n*128 + (k & 63)*2),
             g_WxT + ((size_t)(g*H_ + j0 + hid))*IN_ + k);
    }
    cp_commit(); cp_wait<0>();
    __syncthreads();   // the ONLY full-block sync

    if (w == 8){
        // ----------------- producer warp (lane 0 only) -----------------
        if (lane == 0){
            int pst = 0, pwrap = 0;
            for (int t = 0; t < S_; t++){
                for (int kc = 0; kc < NKC; kc++){
                    const char* src;
                    if (kc < 4){
                        src = g_x + (((size_t)t*2 + bh)*4 + kc)*CHB;
                    } else {
                        if (kc == 4 && t > 0){
                            unsigned v, tgtv = (unsigned)t * GRP_;
                            do { asm volatile("ld.acquire.gpu.global.u32 %0, [%1];\n" : "=r"(v) : "l"(&g_cnt[bh]) : "memory"); }
                            while (v < tgtv);
                        }
                        src = g_h[t & 1][bh] + (kc - 4)*CHB;
                    }
                    if (pwrap > 0) mbar_wait(mb_emp + pst*8, (unsigned)((pwrap - 1) & 1));
                    mbar_expect_tx(mb_full + pst*8, CHB);
                    bulk_g2s(a_smem + pst*CHB, src, CHB, mb_full + pst*8);
                    if (++pst == NSTG){ pst = 0; pwrap++; }
                }
            }
        }
        return;
    }

    // ----------------- compute warps (w = 0..7) ----------------------------
    int wm = w >> 2, wn = w & 3;               // warp tile: rows wm*32+, cols wn*16+
    // bias per (nt, gate) for this thread's hid
    float b4[2][4];
    #pragma unroll
    for (int nt = 0; nt < 2; nt++){
        int hid = wn*4 + nt*2 + (ctid >> 1);
        #pragma unroll
        for (int g = 0; g < 4; g++) b4[nt][g] = bias[g*H_ + j0 + hid];
    }
    float cst[2][2][2];                        // [mt][nt][row] (even-ctid threads)
    #pragma unroll
    for (int a = 0; a < 2; a++)
        #pragma unroll
        for (int b2 = 0; b2 < 2; b2++){ cst[a][b2][0] = 0.f; cst[a][b2][1] = 0.f; }

    int cstg = 0, cwrap = 0;

    for (int t = 0; t < S_; t++){
        float acc[2][2][4];
        #pragma unroll
        for (int mt = 0; mt < 2; mt++)
            #pragma unroll
            for (int nt = 0; nt < 2; nt++){ acc[mt][nt][0]=0; acc[mt][nt][1]=0; acc[mt][nt][2]=0; acc[mt][nt][3]=0; }

        for (int kc = 0; kc < NKC; kc++){
            mbar_wait(mb_full + cstg*8, (unsigned)(cwrap & 1));
            const char* A  = sh + A_OFF + cstg*CHB;
            const char* Bc = (kc < 4) ? (Wxs + kc*CHB) : (Whs + (kc - 4)*CHB);
            #pragma unroll
            for (int kk = 0; kk < 64; kk += 16){
                int cb = (kk + ctid*2)*2;
                uint32_t b0[2], b1[2];
                #pragma unroll
                for (int nt = 0; nt < 2; nt++){
                    int brow = wn*16 + nt*8 + gid;
                    b0[nt] = *(const uint32_t*)(Bc + swz(brow*128 + cb));
                    b1[nt] = *(const uint32_t*)(Bc + swz(brow*128 + cb + 16));
                }
                #pragma unroll
                for (int mt = 0; mt < 2; mt++){
                    int r = wm*32 + mt*16 + gid;
                    uint32_t a0 = *(const uint32_t*)(A + swz( r     *128 + cb     ));
                    uint32_t a1 = *(const uint32_t*)(A + swz((r + 8)*128 + cb     ));
                    uint32_t a2 = *(const uint32_t*)(A + swz( r     *128 + cb + 16));
                    uint32_t a3 = *(const uint32_t*)(A + swz((r + 8)*128 + cb + 16));
                    mma16816(acc[mt][0], a0, a1, a2, a3, b0[0], b1[0]);
                    mma16816(acc[mt][1], a0, a1, a2, a3, b0[1], b1[1]);
                }
            }
            if (lane == 0) mbar_arrive(mb_emp + cstg*8);
            if (++cstg == NSTG){ cstg = 0; cwrap++; }
        }

        // epilogue: pair-exchange gates via shfl, activations, c/h update
        #pragma unroll
        for (int mt = 0; mt < 2; mt++){
            #pragma unroll
            for (int nt = 0; nt < 2; nt++){
                float v0 = acc[mt][nt][0], v1 = acc[mt][nt][1];
                float v2 = acc[mt][nt][2], v3 = acc[mt][nt][3];
                float p0 = __shfl_xor_sync(0xffffffffu, v0, 1);
                float p1 = __shfl_xor_sync(0xffffffffu, v1, 1);
                float p2 = __shfl_xor_sync(0xffffffffu, v2, 1);
                float p3 = __shfl_xor_sync(0xffffffffu, v3, 1);
                if (!(ctid & 1)){
                    int hid = wn*4 + nt*2 + (ctid >> 1);
                    int r0  = wm*32 + mt*16 + gid;
                    {   // row r0: own (f,i) = v0,v1; partner (g,o) = p0,p1
                        float f  = sigm_(v0 + b4[nt][0]);
                        float ii = sigm_(v1 + b4[nt][1]);
                        float gg = tanh_(p0 + b4[nt][2]);
                        float oo = sigm_(p1 + b4[nt][3]);
                        float cn = f*cst[mt][nt][0] + ii*gg;
                        cst[mt][nt][0] = cn;
                        *(__half*)(stg + r0*32 + hid*2) = __float2half(oo * tanh_(cn));
                    }
                    {   // row r0+8
                        float f  = sigm_(v2 + b4[nt][0]);
                        float ii = sigm_(v3 + b4[nt][1]);
                        float gg = tanh_(p2 + b4[nt][2]);
                        float oo = sigm_(p3 + b4[nt][3]);
                        float cn = f*cst[mt][nt][1] + ii*gg;
                        cst[mt][nt][1] = cn;
                        *(__half*)(stg + (r0+8)*32 + hid*2) = __float2half(oo * tanh_(cn));
                    }
                }
            }
        }
        asm volatile("bar.sync 1, 256;\n" ::: "memory");
        // vectorized h store: 64 rows x 32B, 128 threads x 16B
        if (tid < 128){
            int row = tid >> 1, half = tid & 1;
            int4 v = *(const int4*)(stg + row*32 + half*16);
            char* dst = g_h[(t + 1) & 1][bh] + (jgrp >> 2)*CHB;
            *(int4*)(dst + swz(row*128 + (jgrp & 3)*32 + half*16)) = v;
        }
        asm volatile("bar.sync 1, 256;\n" ::: "memory");
        if (tid == 0){
            __threadfence();
            asm volatile("red.release.gpu.global.add.u32 [%0], %1;\n"
                         :: "l"(&g_cnt[bh]), "r"(1u) : "memory");
        }
    }
}

// ---------------- final FC: out = h_T @ Wfc + bfc (fp32) -------------------
__global__ __launch_bounds__(256) void fc_kernel(const float* __restrict__ Wfc,
                                                 const float* __restrict__ bfc,
                                                 float* __restrict__ out){
    __shared__ float hsm[H_];
    int b = blockIdx.x, o = threadIdx.x;
    int bh = b >> 6, row = b & 63;
    for (int k = o; k < H_; k += 256){
        const char* chunk = g_h[0][bh] + (k >> 6)*CHB;   // S even -> buf 0
        hsm[k] = __half2float(*(const __half*)(chunk + swz(row*128 + (k & 63)*2)));
    }
    __syncthreads();
    float s = bfc[o];
    #pragma unroll 8
    for (int k = 0; k < H_; k++) s = fmaf(hsm[k], Wfc[(size_t)k*OUT_ + o], s);
    out[(size_t)b*OUT_ + o] = s;
}

// ---------------- entry -----------------------------------------------------
extern "C" void kernel_launch(void* const* d_in, const int* in_sizes, int n_in,
                              void* d_out, int out_size){
    (void)in_sizes; (void)n_in; (void)out_size;
    const float* x   = (const float*)d_in[0];
    const float* Wx  = (const float*)d_in[1];
    const float* Wh  = (const float*)d_in[2];
    const float* b   = (const float*)d_in[3];
    const float* Wfc = (const float*)d_in[4];
    const float* bfc = (const float*)d_in[5];
    float* out = (float*)d_out;

    cudaFuncSetAttribute(lstm_rec_kernel, cudaFuncAttributeMaxDynamicSharedMemorySize, SMEM_REC);

    conv_x_kernel<<<2048, 256>>>(x);
    conv_w_kernel<<<1024, 256>>>(Wx, Wh);
    zero_h_kernel<<<256, 256>>>();
    lstm_rec_kernel<<<NC_, 288, SMEM_REC>>>(b);
    fc_kernel<<<B_, 256>>>(Wfc, bfc, out);
}

// round 10
// speedup vs baseline: 1.1594x; 1.0644x over previous
#include <cuda_runtime.h>
#include <cuda_fp16.h>
#include <cstdint>
#include <cstddef>

#define B_   128
#define S_   1024
#define IN_  256
#define H_   1024
#define G4_  4096
#define OUT_ 256
#define NC_  128     // CTAs (1/SM): (bh 2) x (jgrp 64)
#define GRP_ 64      // CTAs per batch-half group
#define NSTG 7       // A pipeline stages (8KB each)
#define CHB  8192    // chunk: 64 rows x 64 cols fp16, SW128 image
#define NKC  20      // chunks per step: 4 x + 16 h

// ---------------- device globals -------------------------------------------
// g_x: [t][bh][kc(4)][8KB swizzled]   g_h: [buf][bh][kc(16)][8KB swizzled]
__device__ __align__(1024) char g_x [(size_t)S_*2*4*CHB];   // 64 MB
__device__ __align__(1024) char g_h [2][2][16*CHB];          // 512 KB
__device__ __align__(16)  __half g_WxT[(size_t)G4_*IN_];     // [n][k]
__device__ __align__(16)  __half g_WhT[(size_t)G4_*H_];      // [n][k]
__device__ unsigned g_cnt[2];       // per-group arrival counters (monotonic)

__device__ __host__ __forceinline__ int swz(int o){ return o ^ ((o >> 3) & 0x70); }

// ---------------- helpers ---------------------------------------------------
__device__ __forceinline__ void cp16(void* smem, const void* gmem){
    unsigned s = (unsigned)__cvta_generic_to_shared(smem);
    asm volatile("cp.async.cg.shared.global [%0], [%1], 16;\n" :: "r"(s), "l"(gmem));
}
__device__ __forceinline__ void cp_commit(){ asm volatile("cp.async.commit_group;\n"); }
template<int N> __device__ __forceinline__ void cp_wait(){ asm volatile("cp.async.wait_group %0;\n" :: "n"(N)); }

__device__ __forceinline__ void mbar_init(uint32_t mbar, uint32_t cnt){
    asm volatile("mbarrier.init.shared.b64 [%0], %1;\n" :: "r"(mbar), "r"(cnt) : "memory");
}
__device__ __forceinline__ void mbar_expect_tx(uint32_t mbar, uint32_t tx){
    asm volatile("mbarrier.arrive.expect_tx.shared.b64 _, [%0], %1;\n" :: "r"(mbar), "r"(tx) : "memory");
}
__device__ __forceinline__ void mbar_arrive(uint32_t mbar){
    asm volatile("mbarrier.arrive.shared.b64 _, [%0];\n" :: "r"(mbar) : "memory");
}
__device__ __forceinline__ void bulk_g2s(uint32_t sdst, const void* gsrc, uint32_t bytes, uint32_t mbar){
    asm volatile("cp.async.bulk.shared::cluster.global.mbarrier::complete_tx::bytes [%0], [%1], %2, [%3];\n"
                 :: "r"(sdst), "l"(gsrc), "r"(bytes), "r"(mbar) : "memory");
}
__device__ __forceinline__ void mbar_wait(uint32_t mbar, uint32_t parity){
    asm volatile(
        "{\n\t.reg .pred P1;\n\t"
        "LAB_W_%=:\n\t"
        "mbarrier.try_wait.parity.acquire.cta.shared::cta.b64 P1, [%0], %1;\n\t"
        "@P1 bra LAB_D_%=;\n\t"
        "bra LAB_W_%=;\n\t"
        "LAB_D_%=:\n\t}"
        :: "r"(mbar), "r"(parity) : "memory");
}
__device__ __forceinline__ void mma16816(float* c, uint32_t a0, uint32_t a1, uint32_t a2, uint32_t a3,
                                         uint32_t b0, uint32_t b1){
    asm volatile(
        "mma.sync.aligned.m16n8k16.row.col.f32.f16.f16.f32 "
        "{%0,%1,%2,%3}, {%4,%5,%6,%7}, {%8,%9}, {%0,%1,%2,%3};\n"
        : "+f"(c[0]), "+f"(c[1]), "+f"(c[2]), "+f"(c[3])
        : "r"(a0), "r"(a1), "r"(a2), "r"(a3), "r"(b0), "r"(b1));
}
__device__ __forceinline__ void ldsm4(uint32_t& r0, uint32_t& r1, uint32_t& r2, uint32_t& r3, uint32_t addr){
    asm volatile("ldmatrix.sync.aligned.m8n8.x4.shared.b16 {%0,%1,%2,%3}, [%4];\n"
                 : "=r"(r0), "=r"(r1), "=r"(r2), "=r"(r3) : "r"(addr));
}
__device__ __forceinline__ float sigm_(float x){ return 1.f / (1.f + __expf(-x)); }
__device__ __forceinline__ float tanh_(float x){ return 2.f / (1.f + __expf(-2.f*x)) - 1.f; }

// ---------------- phase 0: converts ----------------------------------------
__global__ void conv_x_kernel(const float* __restrict__ x){
    size_t n = (size_t)B_*S_*IN_;
    for (size_t i = (size_t)blockIdx.x*blockDim.x + threadIdx.x; i < n; i += (size_t)gridDim.x*blockDim.x){
        int k  = (int)(i % IN_);
        size_t bs = i / IN_;
        int s  = (int)(bs % S_);
        int b  = (int)(bs / S_);
        int bh = b >> 6, row = b & 63;
        char* chunk = g_x + (((size_t)s*2 + bh)*4 + (k >> 6))*CHB;
        *(__half*)(chunk + swz(row*128 + (k & 63)*2)) = __float2half(x[i]);
    }
}
__global__ void conv_w_kernel(const float* __restrict__ Wx, const float* __restrict__ Wh){
    size_t n1 = (size_t)G4_*IN_, n2 = (size_t)G4_*H_;
    for (size_t i = (size_t)blockIdx.x*blockDim.x + threadIdx.x; i < n1 + n2; i += (size_t)gridDim.x*blockDim.x){
        if (i < n1){
            int n = (int)(i / IN_), k = (int)(i % IN_);
            g_WxT[i] = __float2half(Wx[(size_t)k*G4_ + n]);
        } else {
            size_t j = i - n1;
            int n = (int)(j / H_), k = (int)(j % H_);
            g_WhT[j] = __float2half(Wh[(size_t)k*G4_ + n]);
        }
    }
}
__global__ void zero_h_kernel(){
    size_t n = sizeof(g_h)/4;
    unsigned* p = (unsigned*)g_h;
    for (size_t i = (size_t)blockIdx.x*blockDim.x + threadIdx.x; i < n; i += (size_t)gridDim.x*blockDim.x)
        p[i] = 0u;
    if (blockIdx.x == 0 && threadIdx.x < 2) g_cnt[threadIdx.x] = 0u;
}

// ---------------- recurrence ------------------------------------------------
// CTA (bh, jgrp): batch rows [bh*64, +64), hidden units [jgrp*16, +16) = 64
// gate cols (col = hid_local*4 + gate). 8 compute warps (tile 32x16) fed by
// ldmatrix.x4 (1 XOR + 3 IADD + 3 LDSM + 4 HMMA per kk-slice). Producer warp
// streams 20 x 8KB bulk chunks/step through a 7-stage mbarrier ring.
constexpr int A_OFF  = 0;
constexpr int WH_OFF = NSTG*CHB;                 // 57344
constexpr int WX_OFF = WH_OFF + 16*CHB;          // 188416
constexpr int ST_OFF = WX_OFF + 4*CHB;           // 221184 (2KB staging)
constexpr int MB_OFF = ST_OFF + 2048;            // 223232
constexpr int SMEM_REC = MB_OFF + 2*NSTG*8 + 16; // 223360

__global__ __launch_bounds__(288,1) void lstm_rec_kernel(const float* __restrict__ bias){
    extern __shared__ __align__(16) char sh[];
    int tid = threadIdx.x, lane = tid & 31, w = tid >> 5;
    int gid = lane >> 2, ctid = lane & 3;
    int bh = blockIdx.x & 1, jgrp = blockIdx.x >> 1;
    int j0 = jgrp * 16;

    uint32_t a_smem  = (uint32_t)__cvta_generic_to_shared(sh + A_OFF);
    uint32_t wh_smem = (uint32_t)__cvta_generic_to_shared(sh + WH_OFF);
    uint32_t wx_smem = (uint32_t)__cvta_generic_to_shared(sh + WX_OFF);
    uint32_t mb_full = (uint32_t)__cvta_generic_to_shared(sh + MB_OFF);   // +8*i
    uint32_t mb_emp  = mb_full + NSTG*8;                                  // +8*i
    char* Whs = sh + WH_OFF;
    char* Wxs = sh + WX_OFF;
    char* stg = sh + ST_OFF;

    if (tid == 0){
        for (int i = 0; i < NSTG; i++){ mbar_init(mb_full + i*8, 1); mbar_init(mb_emp + i*8, 8); }
        asm volatile("fence.proxy.async.shared::cta;\n" ::: "memory");
    }
    // weight slices into swizzled chunk format (row n = hid*4+gate, 64 rows)
    for (int idx = tid; idx < 64*128; idx += 288){
        int n = idx >> 7, u = idx & 127;
        int hid = n >> 2, g = n & 3, k = u*8;
        cp16(Whs + (k >> 6)*CHB + swz(n*128 + (k & 63)*2),
             g_WhT + ((size_t)(g*H_ + j0 + hid))*H_ + k);
    }
    for (int idx = tid; idx < 64*32; idx += 288){
        int n = idx >> 5, u = idx & 31;
        int hid = n >> 2, g = n & 3, k = u*8;
        cp16(Wxs + (k >> 6)*CHB + swz(n*128 + (k & 63)*2),
             g_WxT + ((size_t)(g*H_ + j0 + hid))*IN_ + k);
    }
    cp_commit(); cp_wait<0>();
    __syncthreads();   // the ONLY full-block sync

    if (w == 8){
        // ----------------- producer warp (lane 0 only) -----------------
        if (lane == 0){
            int pst = 0, pwrap = 0;
            for (int t = 0; t < S_; t++){
                for (int kc = 0; kc < NKC; kc++){
                    const char* src;
                    if (kc < 4){
                        src = g_x + (((size_t)t*2 + bh)*4 + kc)*CHB;
                    } else {
                        if (kc == 4 && t > 0){
                            unsigned v, tgtv = (unsigned)t * GRP_;
                            do { asm volatile("ld.acquire.gpu.global.u32 %0, [%1];\n" : "=r"(v) : "l"(&g_cnt[bh]) : "memory"); }
                            while (v < tgtv);
                        }
                        src = g_h[t & 1][bh] + (kc - 4)*CHB;
                    }
                    if (pwrap > 0) mbar_wait(mb_emp + pst*8, (unsigned)((pwrap - 1) & 1));
                    mbar_expect_tx(mb_full + pst*8, CHB);
                    bulk_g2s(a_smem + pst*CHB, src, CHB, mb_full + pst*8);
                    if (++pst == NSTG){ pst = 0; pwrap++; }
                }
            }
        }
        return;
    }

    // ----------------- compute warps (w = 0..7) ----------------------------
    int wm = w >> 2, wn = w & 3;               // warp tile: rows wm*32+, cols wn*16+

    // ldmatrix per-lane geometry: lane -> (matrix, row-in-matrix)
    int mat = lane >> 3, rin = lane & 7;
    uint32_t xorv = (uint32_t)(rin << 4);                 // swizzle XOR (row-only)
    uint32_t ac   = (uint32_t)((mat >> 1) << 4);          // col half: 0 or 16 bytes
    uint32_t arow0 = (uint32_t)((wm*32 +  0 + (mat & 1)*8 + rin) * 128);
    uint32_t arow1 = (uint32_t)((wm*32 + 16 + (mat & 1)*8 + rin) * 128);
    uint32_t brow  = (uint32_t)((wn*16 +      (mat & 1)*8 + rin) * 128);

    // bias per (nt, gate) for this thread's hid
    float b4[2][4];
    #pragma unroll
    for (int nt = 0; nt < 2; nt++){
        int hid = wn*4 + nt*2 + (ctid >> 1);
        #pragma unroll
        for (int g = 0; g < 4; g++) b4[nt][g] = bias[g*H_ + j0 + hid];
    }
    float cst[2][2][2];                        // [mt][nt][row] (even-ctid threads)
    #pragma unroll
    for (int a = 0; a < 2; a++)
        #pragma unroll
        for (int b2 = 0; b2 < 2; b2++){ cst[a][b2][0] = 0.f; cst[a][b2][1] = 0.f; }

    int cstg = 0, cwrap = 0;

    for (int t = 0; t < S_; t++){
        float acc[2][2][4];
        #pragma unroll
        for (int mt = 0; mt < 2; mt++)
            #pragma unroll
            for (int nt = 0; nt < 2; nt++){ acc[mt][nt][0]=0; acc[mt][nt][1]=0; acc[mt][nt][2]=0; acc[mt][nt][3]=0; }

        for (int kc = 0; kc < NKC; kc++){
            mbar_wait(mb_full + cstg*8, (unsigned)(cwrap & 1));
            uint32_t Ab0 = a_smem + (uint32_t)cstg*CHB + arow0;
            uint32_t Ab1 = a_smem + (uint32_t)cstg*CHB + arow1;
            uint32_t Bb  = ((kc < 4) ? (wx_smem + (uint32_t)kc*CHB)
                                     : (wh_smem + (uint32_t)(kc - 4)*CHB)) + brow;
            #pragma unroll
            for (int kk2 = 0; kk2 < 128; kk2 += 32){
                uint32_t xt = ((uint32_t)kk2 + ac) ^ xorv;
                uint32_t a0,a1,a2,a3, e0,e1,e2,e3, c0,c1,c2,c3;
                ldsm4(a0,a1,a2,a3, Ab0 + xt);
                ldsm4(e0,e1,e2,e3, Ab1 + xt);
                ldsm4(c0,c1,c2,c3, Bb  + xt);
                mma16816(acc[0][0], a0,a1,a2,a3, c0, c2);
                mma16816(acc[0][1], a0,a1,a2,a3, c1, c3);
                mma16816(acc[1][0], e0,e1,e2,e3, c0, c2);
                mma16816(acc[1][1], e0,e1,e2,e3, c1, c3);
            }
            if (lane == 0) mbar_arrive(mb_emp + cstg*8);
            if (++cstg == NSTG){ cstg = 0; cwrap++; }
        }

        // epilogue: pair-exchange gates via shfl, activations, c/h update
        #pragma unroll
        for (int mt = 0; mt < 2; mt++){
            #pragma unroll
            for (int nt = 0; nt < 2; nt++){
                float v0 = acc[mt][nt][0], v1 = acc[mt][nt][1];
                float v2 = acc[mt][nt][2], v3 = acc[mt][nt][3];
                float p0 = __shfl_xor_sync(0xffffffffu, v0, 1);
                float p1 = __shfl_xor_sync(0xffffffffu, v1, 1);
                float p2 = __shfl_xor_sync(0xffffffffu, v2, 1);
                float p3 = __shfl_xor_sync(0xffffffffu, v3, 1);
                if (!(ctid & 1)){
                    int hid = wn*4 + nt*2 + (ctid >> 1);
                    int r0  = wm*32 + mt*16 + gid;
                    {   // row r0: own (f,i) = v0,v1; partner (g,o) = p0,p1
                        float f  = sigm_(v0 + b4[nt][0]);
                        float ii = sigm_(v1 + b4[nt][1]);
                        float gg = tanh_(p0 + b4[nt][2]);
                        float oo = sigm_(p1 + b4[nt][3]);
                        float cn = f*cst[mt][nt][0] + ii*gg;
                        cst[mt][nt][0] = cn;
                        *(__half*)(stg + r0*32 + hid*2) = __float2half(oo * tanh_(cn));
                    }
                    {   // row r0+8
                        float f  = sigm_(v2 + b4[nt][0]);
                        float ii = sigm_(v3 + b4[nt][1]);
                        float gg = tanh_(p2 + b4[nt][2]);
                        float oo = sigm_(p3 + b4[nt][3]);
                        float cn = f*cst[mt][nt][1] + ii*gg;
                        cst[mt][nt][1] = cn;
                        *(__half*)(stg + (r0+8)*32 + hid*2) = __float2half(oo * tanh_(cn));
                    }
                }
            }
        }
        asm volatile("bar.sync 1, 256;\n" ::: "memory");
        // vectorized h store: 64 rows x 32B, 128 threads x 16B
        if (tid < 128){
            int row = tid >> 1, half = tid & 1;
            int4 v = *(const int4*)(stg + row*32 + half*16);
            char* dst = g_h[(t + 1) & 1][bh] + (jgrp >> 2)*CHB;
            *(int4*)(dst + swz(row*128 + (jgrp & 3)*32 + half*16)) = v;
        }
        asm volatile("bar.sync 1, 256;\n" ::: "memory");
        if (tid == 0){
            __threadfence();
            asm volatile("red.release.gpu.global.add.u32 [%0], %1;\n"
                         :: "l"(&g_cnt[bh]), "r"(1u) : "memory");
        }
    }
}

// ---------------- final FC: out = h_T @ Wfc + bfc (fp32) -------------------
__global__ __launch_bounds__(256) void fc_kernel(const float* __restrict__ Wfc,
                                                 const float* __restrict__ bfc,
                                                 float* __restrict__ out){
    __shared__ float hsm[H_];
    int b = blockIdx.x, o = threadIdx.x;
    int bh = b >> 6, row = b & 63;
    for (int k = o; k < H_; k += 256){
        const char* chunk = g_h[0][bh] + (k >> 6)*CHB;   // S even -> buf 0
        hsm[k] = __half2float(*(const __half*)(chunk + swz(row*128 + (k & 63)*2)));
    }
    __syncthreads();
    float s = bfc[o];
    #pragma unroll 8
    for (int k = 0; k < H_; k++) s = fmaf(hsm[k], Wfc[(size_t)k*OUT_ + o], s);
    out[(size_t)b*OUT_ + o] = s;
}

// ---------------- entry -----------------------------------------------------
extern "C" void kernel_launch(void* const* d_in, const int* in_sizes, int n_in,
                              void* d_out, int out_size){
    (void)in_sizes; (void)n_in; (void)out_size;
    const float* x   = (const float*)d_in[0];
    const float* Wx  = (const float*)d_in[1];
    const float* Wh  = (const float*)d_in[2];
    const float* b   = (const float*)d_in[3];
    const float* Wfc = (const float*)d_in[4];
    const float* bfc = (const float*)d_in[5];
    float* out = (float*)d_out;

    cudaFuncSetAttribute(lstm_rec_kernel, cudaFuncAttributeMaxDynamicSharedMemorySize, SMEM_REC);

    conv_x_kernel<<<2048, 256>>>(x);
    conv_w_kernel<<<1024, 256>>>(Wx, Wh);
    zero_h_kernel<<<256, 256>>>();
    lstm_rec_kernel<<<NC_, 288, SMEM_REC>>>(b);
    fc_kernel<<<B_, 256>>>(Wfc, bfc, out);
}

// round 11
// speedup vs baseline: 1.4714x; 1.2691x over previous
#include <cuda_runtime.h>
#include <cuda_fp16.h>
#include <cstdint>
#include <cstddef>

#define B_   128
#define S_   1024
#define IN_  256
#define H_   1024
#define G4_  4096
#define OUT_ 256
#define NC_  128     // CTAs (1/SM): (bh 2) x (jgrp 64)
#define GRP_ 64      // CTAs per batch-half group
#define ARR_ (GRP_*8)// warp-level arrivals per group per step (512)
#define NSTG 8       // A pipeline stages (8KB each)
#define CHB  8192    // chunk: 64 rows x 64 cols fp16, SW128 image
#define NKC  20      // chunks per step: 4 x + 16 h

// ---------------- device globals -------------------------------------------
// g_x: [t][bh][kc(4)][8KB swizzled]   g_h: [buf][bh][kc(16)][8KB swizzled]
__device__ __align__(1024) char g_x [(size_t)S_*2*4*CHB];   // 64 MB
__device__ __align__(1024) char g_h [2][2][16*CHB];          // 512 KB
__device__ __align__(16)  __half g_WxT[(size_t)G4_*IN_];     // [n][k]
__device__ __align__(16)  __half g_WhT[(size_t)G4_*H_];      // [n][k]
__device__ unsigned g_cnt[2];       // per-group warp-arrival counters

__device__ __host__ __forceinline__ int swz(int o){ return o ^ ((o >> 3) & 0x70); }

// ---------------- helpers ---------------------------------------------------
__device__ __forceinline__ void cp16(void* smem, const void* gmem){
    unsigned s = (unsigned)__cvta_generic_to_shared(smem);
    asm volatile("cp.async.cg.shared.global [%0], [%1], 16;\n" :: "r"(s), "l"(gmem));
}
__device__ __forceinline__ void cp_commit(){ asm volatile("cp.async.commit_group;\n"); }
template<int N> __device__ __forceinline__ void cp_wait(){ asm volatile("cp.async.wait_group %0;\n" :: "n"(N)); }

__device__ __forceinline__ void mbar_init(uint32_t mbar, uint32_t cnt){
    asm volatile("mbarrier.init.shared.b64 [%0], %1;\n" :: "r"(mbar), "r"(cnt) : "memory");
}
__device__ __forceinline__ void mbar_expect_tx(uint32_t mbar, uint32_t tx){
    asm volatile("mbarrier.arrive.expect_tx.shared.b64 _, [%0], %1;\n" :: "r"(mbar), "r"(tx) : "memory");
}
__device__ __forceinline__ void mbar_arrive(uint32_t mbar){
    asm volatile("mbarrier.arrive.shared.b64 _, [%0];\n" :: "r"(mbar) : "memory");
}
__device__ __forceinline__ void bulk_g2s(uint32_t sdst, const void* gsrc, uint32_t bytes, uint32_t mbar){
    asm volatile("cp.async.bulk.shared::cluster.global.mbarrier::complete_tx::bytes [%0], [%1], %2, [%3];\n"
                 :: "r"(sdst), "l"(gsrc), "r"(bytes), "r"(mbar) : "memory");
}
__device__ __forceinline__ void mbar_wait(uint32_t mbar, uint32_t parity){
    asm volatile(
        "{\n\t.reg .pred P1;\n\t"
        "LAB_W_%=:\n\t"
        "mbarrier.try_wait.parity.acquire.cta.shared::cta.b64 P1, [%0], %1;\n\t"
        "@P1 bra LAB_D_%=;\n\t"
        "bra LAB_W_%=;\n\t"
        "LAB_D_%=:\n\t}"
        :: "r"(mbar), "r"(parity) : "memory");
}
__device__ __forceinline__ void mma16816(float* c, uint32_t a0, uint32_t a1, uint32_t a2, uint32_t a3,
                                         uint32_t b0, uint32_t b1){
    asm volatile(
        "mma.sync.aligned.m16n8k16.row.col.f32.f16.f16.f32 "
        "{%0,%1,%2,%3}, {%4,%5,%6,%7}, {%8,%9}, {%0,%1,%2,%3};\n"
        : "+f"(c[0]), "+f"(c[1]), "+f"(c[2]), "+f"(c[3])
        : "r"(a0), "r"(a1), "r"(a2), "r"(a3), "r"(b0), "r"(b1));
}
__device__ __forceinline__ void ldsm4(uint32_t& r0, uint32_t& r1, uint32_t& r2, uint32_t& r3, uint32_t addr){
    asm volatile("ldmatrix.sync.aligned.m8n8.x4.shared.b16 {%0,%1,%2,%3}, [%4];\n"
                 : "=r"(r0), "=r"(r1), "=r"(r2), "=r"(r3) : "r"(addr));
}
__device__ __forceinline__ float sigm_(float x){ return 1.f / (1.f + __expf(-x)); }
__device__ __forceinline__ float tanh_(float x){ return 2.f / (1.f + __expf(-2.f*x)) - 1.f; }

// ---------------- phase 0: converts ----------------------------------------
__global__ void conv_x_kernel(const float* __restrict__ x){
    size_t n = (size_t)B_*S_*IN_;
    for (size_t i = (size_t)blockIdx.x*blockDim.x + threadIdx.x; i < n; i += (size_t)gridDim.x*blockDim.x){
        int k  = (int)(i % IN_);
        size_t bs = i / IN_;
        int s  = (int)(bs % S_);
        int b  = (int)(bs / S_);
        int bh = b >> 6, row = b & 63;
        char* chunk = g_x + (((size_t)s*2 + bh)*4 + (k >> 6))*CHB;
        *(__half*)(chunk + swz(row*128 + (k & 63)*2)) = __float2half(x[i]);
    }
}
__global__ void conv_w_kernel(const float* __restrict__ Wx, const float* __restrict__ Wh){
    size_t n1 = (size_t)G4_*IN_, n2 = (size_t)G4_*H_;
    for (size_t i = (size_t)blockIdx.x*blockDim.x + threadIdx.x; i < n1 + n2; i += (size_t)gridDim.x*blockDim.x){
        if (i < n1){
            int n = (int)(i / IN_), k = (int)(i % IN_);
            g_WxT[i] = __float2half(Wx[(size_t)k*G4_ + n]);
        } else {
            size_t j = i - n1;
            int n = (int)(j / H_), k = (int)(j % H_);
            g_WhT[j] = __float2half(Wh[(size_t)k*G4_ + n]);
        }
    }
}
__global__ void zero_h_kernel(){
    size_t n = sizeof(g_h)/4;
    unsigned* p = (unsigned*)g_h;
    for (size_t i = (size_t)blockIdx.x*blockDim.x + threadIdx.x; i < n; i += (size_t)gridDim.x*blockDim.x)
        p[i] = 0u;
    if (blockIdx.x == 0 && threadIdx.x < 2) g_cnt[threadIdx.x] = 0u;
}

// ---------------- recurrence ------------------------------------------------
// CTA (bh, jgrp): batch rows [bh*64, +64), hidden units [jgrp*16, +16) = 64
// gate cols (col = hid_local*4 + gate). 8 fully-decoupled compute warps
// (tile 32x16, ldmatrix-fed); NO block syncs in the loop. Warp-level global
// arrivals (red.release per warp); x-part of t+1 computed in barrier shadow.
constexpr int A_OFF  = 0;
constexpr int WH_OFF = NSTG*CHB;                 // 65536
constexpr int WX_OFF = WH_OFF + 16*CHB;          // 196608
constexpr int MB_OFF = WX_OFF + 4*CHB;           // 229376
constexpr int SMEM_REC = MB_OFF + 2*NSTG*8 + 16; // 229520

__global__ __launch_bounds__(288,1) void lstm_rec_kernel(const float* __restrict__ bias){
    extern __shared__ __align__(16) char sh[];
    int tid = threadIdx.x, lane = tid & 31, w = tid >> 5;
    int gid = lane >> 2, ctid = lane & 3;
    int bh = blockIdx.x & 1, jgrp = blockIdx.x >> 1;
    int j0 = jgrp * 16;

    uint32_t a_smem  = (uint32_t)__cvta_generic_to_shared(sh + A_OFF);
    uint32_t wh_smem = (uint32_t)__cvta_generic_to_shared(sh + WH_OFF);
    uint32_t wx_smem = (uint32_t)__cvta_generic_to_shared(sh + WX_OFF);
    uint32_t mb_full = (uint32_t)__cvta_generic_to_shared(sh + MB_OFF);   // +8*i
    uint32_t mb_emp  = mb_full + NSTG*8;                                  // +8*i
    char* Whs = sh + WH_OFF;
    char* Wxs = sh + WX_OFF;

    if (tid == 0){
        for (int i = 0; i < NSTG; i++){ mbar_init(mb_full + i*8, 1); mbar_init(mb_emp + i*8, 8); }
        asm volatile("fence.proxy.async.shared::cta;\n" ::: "memory");
    }
    // weight slices into swizzled chunk format (row n = hid*4+gate, 64 rows)
    for (int idx = tid; idx < 64*128; idx += 288){
        int n = idx >> 7, u = idx & 127;
        int hid = n >> 2, g = n & 3, k = u*8;
        cp16(Whs + (k >> 6)*CHB + swz(n*128 + (k & 63)*2),
             g_WhT + ((size_t)(g*H_ + j0 + hid))*H_ + k);
    }
    for (int idx = tid; idx < 64*32; idx += 288){
        int n = idx >> 5, u = idx & 31;
        int hid = n >> 2, g = n & 3, k = u*8;
        cp16(Wxs + (k >> 6)*CHB + swz(n*128 + (k & 63)*2),
             g_WxT + ((size_t)(g*H_ + j0 + hid))*IN_ + k);
    }
    cp_commit(); cp_wait<0>();
    __syncthreads();   // the ONLY full-block sync

    if (w == 8){
        // ----------------- producer warp (lane 0 only) -----------------
        if (lane == 0){
            int pst = 0, pwrap = 0;
            auto issue = [&](const char* src){
                if (pwrap > 0) mbar_wait(mb_emp + pst*8, (unsigned)((pwrap - 1) & 1));
                mbar_expect_tx(mb_full + pst*8, CHB);
                bulk_g2s(a_smem + pst*CHB, src, CHB, mb_full + pst*8);
                if (++pst == NSTG){ pst = 0; pwrap++; }
            };
            for (int kc = 0; kc < 4; kc++)
                issue(g_x + ((size_t)0*2 + bh)*4*CHB + kc*CHB);
            for (int t = 0; t < S_; t++){
                if (t > 0){
                    unsigned v, tgtv = (unsigned)t * ARR_;
                    do { asm volatile("ld.acquire.gpu.global.u32 %0, [%1];\n" : "=r"(v) : "l"(&g_cnt[bh]) : "memory"); }
                    while (v < tgtv);
                }
                for (int kc = 0; kc < 16; kc++)
                    issue(g_h[t & 1][bh] + kc*CHB);
                if (t + 1 < S_)
                    for (int kc = 0; kc < 4; kc++)
                        issue(g_x + (((size_t)(t+1)*2 + bh)*4 + kc)*CHB);
            }
        }
        return;
    }

    // ----------------- compute warps (w = 0..7, fully decoupled) -----------
    int wm = w >> 2, wn = w & 3;               // warp tile: rows wm*32+, cols wn*16+

    // ldmatrix per-lane geometry
    int mat = lane >> 3, rin = lane & 7;
    uint32_t xorv = (uint32_t)(rin << 4);
    uint32_t ac   = (uint32_t)((mat >> 1) << 4);
    uint32_t arow0 = (uint32_t)((wm*32 +  0 + (mat & 1)*8 + rin) * 128);
    uint32_t arow1 = (uint32_t)((wm*32 + 16 + (mat & 1)*8 + rin) * 128);
    uint32_t brow  = (uint32_t)((wn*16 +      (mat & 1)*8 + rin) * 128);

    int odd = ctid & 1;
    // bias per (nt, gate); hid = wn*4 + nt*2 + (ctid>>1), same for shfl pair
    float b4[2][4];
    #pragma unroll
    for (int nt = 0; nt < 2; nt++){
        int hid = wn*4 + nt*2 + (ctid >> 1);
        #pragma unroll
        for (int g = 0; g < 4; g++) b4[nt][g] = bias[g*H_ + j0 + hid];
    }
    float cst[2][2];                           // one c per lane per (mt,nt)
    cst[0][0]=0.f; cst[0][1]=0.f; cst[1][0]=0.f; cst[1][1]=0.f;

    float acc[2][2][4];
    int cstg = 0, cwrap = 0;

    auto zacc = [&](){
        #pragma unroll
        for (int mt = 0; mt < 2; mt++)
            #pragma unroll
            for (int nt = 0; nt < 2; nt++){ acc[mt][nt][0]=0; acc[mt][nt][1]=0; acc[mt][nt][2]=0; acc[mt][nt][3]=0; }
    };
    auto chunk = [&](uint32_t wsmem, int kc){
        mbar_wait(mb_full + cstg*8, (unsigned)(cwrap & 1));
        uint32_t Ab0 = a_smem + (uint32_t)cstg*CHB + arow0;
        uint32_t Ab1 = a_smem + (uint32_t)cstg*CHB + arow1;
        uint32_t Bb  = wsmem + (uint32_t)kc*CHB + brow;
        #pragma unroll
        for (int kk2 = 0; kk2 < 128; kk2 += 32){
            uint32_t xt = ((uint32_t)kk2 + ac) ^ xorv;
            uint32_t a0,a1,a2,a3, e0,e1,e2,e3, c0,c1,c2,c3;
            ldsm4(a0,a1,a2,a3, Ab0 + xt);
            ldsm4(e0,e1,e2,e3, Ab1 + xt);
            ldsm4(c0,c1,c2,c3, Bb  + xt);
            mma16816(acc[0][0], a0,a1,a2,a3, c0, c2);
            mma16816(acc[0][1], a0,a1,a2,a3, c1, c3);
            mma16816(acc[1][0], e0,e1,e2,e3, c0, c2);
            mma16816(acc[1][1], e0,e1,e2,e3, c1, c3);
        }
        if (lane == 0) mbar_arrive(mb_emp + cstg*8);
        if (++cstg == NSTG){ cstg = 0; cwrap++; }
    };

    // prologue: x-part of t=0
    zacc();
    #pragma unroll
    for (int kc = 0; kc < 4; kc++) chunk(wx_smem, kc);

    for (int t = 0; t < S_; t++){
        for (int kc = 0; kc < 16; kc++) chunk(wh_smem, kc);

        // epilogue: all 32 lanes active (even lane -> row gid, odd -> gid+8)
        char* dst = g_h[(t + 1) & 1][bh] + (jgrp >> 2)*CHB;
        #pragma unroll
        for (int mt = 0; mt < 2; mt++){
            #pragma unroll
            for (int nt = 0; nt < 2; nt++){
                float v0 = acc[mt][nt][0], v1 = acc[mt][nt][1];
                float v2 = acc[mt][nt][2], v3 = acc[mt][nt][3];
                float p0 = __shfl_xor_sync(0xffffffffu, v0, 1);
                float p1 = __shfl_xor_sync(0xffffffffu, v1, 1);
                float p2 = __shfl_xor_sync(0xffffffffu, v2, 1);
                float p3 = __shfl_xor_sync(0xffffffffu, v3, 1);
                float f  = odd ? p2 : v0;
                float ii = odd ? p3 : v1;
                float gg = odd ? v2 : p0;
                float oo = odd ? v3 : p1;
                float fg = sigm_(f  + b4[nt][0]);
                float ig = sigm_(ii + b4[nt][1]);
                float gv = tanh_(gg + b4[nt][2]);
                float ov = sigm_(oo + b4[nt][3]);
                float cn = fg*cst[mt][nt] + ig*gv;
                cst[mt][nt] = cn;
                unsigned mine = (unsigned)__half_as_ushort(__float2half(ov * tanh_(cn)));
                unsigned part = __shfl_xor_sync(0xffffffffu, mine, 2);
                if (ctid < 2){
                    unsigned packed = mine | (part << 16);   // hid pair (lo, hi)
                    int r = wm*32 + mt*16 + gid + (odd << 3);
                    int cb = (jgrp & 3)*32 + wn*8 + nt*4;
                    *(uint32_t*)(dst + swz(r*128 + cb)) = packed;
                }
            }
        }
        __syncwarp();                    // intra-warp HB (fence.cta semantics)
        if (lane == 0)
            asm volatile("red.release.gpu.global.add.u32 [%0], %1;\n"
                         :: "l"(&g_cnt[bh]), "r"(1u) : "memory");

        // x-part of t+1 in the barrier shadow
        if (t + 1 < S_){
            zacc();
            #pragma unroll
            for (int kc = 0; kc < 4; kc++) chunk(wx_smem, kc);
        }
    }
}

// ---------------- final FC: out = h_T @ Wfc + bfc (fp32) -------------------
__global__ __launch_bounds__(256) void fc_kernel(const float* __restrict__ Wfc,
                                                 const float* __restrict__ bfc,
                                                 float* __restrict__ out){
    __shared__ float hsm[H_];
    int b = blockIdx.x, o = threadIdx.x;
    int bh = b >> 6, row = b & 63;
    for (int k = o; k < H_; k += 256){
        const char* chunk = g_h[0][bh] + (k >> 6)*CHB;   // S even -> buf 0
        hsm[k] = __half2float(*(const __half*)(chunk + swz(row*128 + (k & 63)*2)));
    }
    __syncthreads();
    float s = bfc[o];
    #pragma unroll 8
    for (int k = 0; k < H_; k++) s = fmaf(hsm[k], Wfc[(size_t)k*OUT_ + o], s);
    out[(size_t)b*OUT_ + o] = s;
}

// ---------------- entry -----------------------------------------------------
extern "C" void kernel_launch(void* const* d_in, const int* in_sizes, int n_in,
                              void* d_out, int out_size){
    (void)in_sizes; (void)n_in; (void)out_size;
    const float* x   = (const float*)d_in[0];
    const float* Wx  = (const float*)d_in[1];
    const float* Wh  = (const float*)d_in[2];
    const float* b   = (const float*)d_in[3];
    const float* Wfc = (const float*)d_in[4];
    const float* bfc = (const float*)d_in[5];
    float* out = (float*)d_out;

    cudaFuncSetAttribute(lstm_rec_kernel, cudaFuncAttributeMaxDynamicSharedMemorySize, SMEM_REC);

    conv_x_kernel<<<2048, 256>>>(x);
    conv_w_kernel<<<1024, 256>>>(Wx, Wh);
    zero_h_kernel<<<256, 256>>>();
    lstm_rec_kernel<<<NC_, 288, SMEM_REC>>>(b);
    fc_kernel<<<B_, 256>>>(Wfc, bfc, out);
}